// round 1
// baseline (speedup 1.0000x reference)
#include <cuda_runtime.h>

// ---------------------------------------------------------------------------
// Math: the GAT collapses. Node features are uniform per batch item, so the
// attention-weighted aggregation (softmax weights sum to 1; self-loops ensure
// every dst has >=1 edge) returns the (uniform) transformed feature exactly.
// Whole model == small MLP per batch row:
//   h  = relu(W_in x + b_in)
//   g  = relu(gat_W[l] g + gat_b[l])  for l = 0..2
//   f  = relu(W_fuse [g ; emb[ci]] + b_fuse)
//   p  = relu chain W_p1,W_p2 -> price = W_p3 p + b_p3
//   d  = relu chain W_d1,W_d2 -> dir   = sigmoid(W_d3 d + b_d3)
// Output: out[0..63] = price, out[64..127] = direction.
// ---------------------------------------------------------------------------

typedef unsigned long long ULL;

__device__ __forceinline__ ULL pack2f(float x, float y) {
    ULL r; asm("mov.b64 %0, {%1, %2};" : "=l"(r) : "f"(x), "f"(y)); return r;
}
__device__ __forceinline__ void ffma2(ULL& d, ULL a, ULL b) {
    asm("fma.rn.f32x2 %0, %1, %2, %0;" : "+l"(d) : "l"(a), "l"(b));
}
__device__ __forceinline__ void fadd2(ULL& d, ULL a) {
    asm("add.rn.f32x2 %0, %1, %0;" : "+l"(d) : "l"(a));
}
__device__ __forceinline__ float2 unpack2f(ULL v) {
    float2 f; asm("mov.b64 {%0, %1}, %2;" : "=f"(f.x), "=f"(f.y) : "l"(v)); return f;
}

// Packed-weight scratch. Layout per matrix [O x K] (row-major src):
//   dst[off + (k>>2)*O*4 + o*4 + (k&3)] = W[o*K + k]
// so a thread t reading longlong2 at (k4*O + t) gets 4 consecutive k's of its
// row, coalesced across the warp (32 lanes x 16B contiguous).
#define OFF_IN   0        // W_in          256 x  64
#define OFF_G0   16384    // gat_W[0]      256 x 256
#define OFF_G1   81920    // gat_W[1]
#define OFF_G2   147456   // gat_W[2]
#define OFF_F    212992   // W_fuse        256 x 320
#define OFF_S1   294912   // [W_p1 ; W_d1] 256 x 256 (rows 0-127 p1, 128-255 d1)
#define OFF_P2   360448   // W_p2           64 x 128
#define OFF_D2   368640   // W_d2           64 x 128
#define PACK_TOTAL 376832

__device__ __align__(16) float g_packed[PACK_TOTAL];

__global__ void pack_kernel(const float* __restrict__ W_in,
                            const float* __restrict__ gat_W,
                            const float* __restrict__ W_fuse,
                            const float* __restrict__ W_p1,
                            const float* __restrict__ W_d1,
                            const float* __restrict__ W_p2,
                            const float* __restrict__ W_d2) {
    int stride = gridDim.x * blockDim.x;
    for (int e = blockIdx.x * blockDim.x + threadIdx.x; e < PACK_TOTAL; e += stride) {
        const float* src; int le, K, Ocomb, obase, off;
        if (e < 16384)       { src = W_in;           le = e;          K = 64;  Ocomb = 256; obase = 0;   off = OFF_IN; }
        else if (e < 81920)  { src = gat_W;          le = e - 16384;  K = 256; Ocomb = 256; obase = 0;   off = OFF_G0; }
        else if (e < 147456) { src = gat_W + 65536;  le = e - 81920;  K = 256; Ocomb = 256; obase = 0;   off = OFF_G1; }
        else if (e < 212992) { src = gat_W + 131072; le = e - 147456; K = 256; Ocomb = 256; obase = 0;   off = OFF_G2; }
        else if (e < 294912) { src = W_fuse;         le = e - 212992; K = 320; Ocomb = 256; obase = 0;   off = OFF_F;  }
        else if (e < 327680) { src = W_p1;           le = e - 294912; K = 256; Ocomb = 256; obase = 0;   off = OFF_S1; }
        else if (e < 360448) { src = W_d1;           le = e - 327680; K = 256; Ocomb = 256; obase = 128; off = OFF_S1; }
        else if (e < 368640) { src = W_p2;           le = e - 360448; K = 128; Ocomb = 64;  obase = 0;   off = OFF_P2; }
        else                 { src = W_d2;           le = e - 368640; K = 128; Ocomb = 64;  obase = 0;   off = OFF_D2; }
        int o = le / K;
        int k = le - o * K;
        g_packed[off + (k >> 2) * (Ocomb * 4) + (obase + o) * 4 + (k & 3)] = src[le];
    }
}

// Dual-row dot product: result.x = bias + dot(W[t,:], s0), result.y likewise s1.
// f32x2 lanes carry two adjacent-k partial chains (no per-element broadcast).
template<int O, int K>
__device__ __forceinline__ float2 dot2(const float* __restrict__ Pw, int t,
                                       const float* __restrict__ s0,
                                       const float* __restrict__ s1,
                                       float bias) {
    const longlong2* wp = (const longlong2*)Pw;
    ULL a0 = pack2f(bias, 0.f);
    ULL a1 = pack2f(bias, 0.f);
    ULL b0 = pack2f(0.f, 0.f);
    ULL b1 = pack2f(0.f, 0.f);
    #pragma unroll 4
    for (int i = 0; i < K / 8; i++) {
        longlong2 w0 = wp[(2 * i) * O + t];         // k = 8i .. 8i+3
        longlong2 w1 = wp[(2 * i + 1) * O + t];     // k = 8i+4 .. 8i+7
        longlong2 sx0 = *(const longlong2*)(s0 + 8 * i);
        longlong2 sx1 = *(const longlong2*)(s0 + 8 * i + 4);
        longlong2 sy0 = *(const longlong2*)(s1 + 8 * i);
        longlong2 sy1 = *(const longlong2*)(s1 + 8 * i + 4);
        ffma2(a0, (ULL)w0.x, (ULL)sx0.x);
        ffma2(a0, (ULL)w0.y, (ULL)sx0.y);
        ffma2(b0, (ULL)w1.x, (ULL)sx1.x);
        ffma2(b0, (ULL)w1.y, (ULL)sx1.y);
        ffma2(a1, (ULL)w0.x, (ULL)sy0.x);
        ffma2(a1, (ULL)w0.y, (ULL)sy0.y);
        ffma2(b1, (ULL)w1.x, (ULL)sy1.x);
        ffma2(b1, (ULL)w1.y, (ULL)sy1.y);
    }
    fadd2(a0, b0);
    fadd2(a1, b1);
    float2 f0 = unpack2f(a0), f1 = unpack2f(a1);
    return make_float2(f0.x + f0.y, f1.x + f1.y);
}

__global__ __launch_bounds__(256) void gat_collapse_kernel(
    const float* __restrict__ x, const int* __restrict__ cidx,
    const float* __restrict__ b_in, const float* __restrict__ gat_b,
    const float* __restrict__ emb, const float* __restrict__ b_fuse,
    const float* __restrict__ b_p1, const float* __restrict__ b_d1,
    const float* __restrict__ b_p2, const float* __restrict__ b_d2,
    const float* __restrict__ W_p3, const float* __restrict__ b_p3,
    const float* __restrict__ W_d3, const float* __restrict__ b_d3,
    float* __restrict__ out) {

    __shared__ __align__(16) float sx0[64], sx1[64];
    __shared__ __align__(16) float A0[320], A1[320], B0[320], B1[320];

    const int t = threadIdx.x;
    const int r0 = blockIdx.x * 2;
    const int r1 = r0 + 1;

    if (t < 64)       sx0[t]      = x[r0 * 64 + t];
    else if (t < 128) sx1[t - 64] = x[r1 * 64 + (t - 64)];
    __syncthreads();

    // ---- input layer: [256 x 64] ----
    {
        float2 v = dot2<256, 64>(g_packed + OFF_IN, t, sx0, sx1, b_in[t]);
        A0[t] = fmaxf(v.x, 0.f); A1[t] = fmaxf(v.y, 0.f);
    }
    __syncthreads();

    // ---- collapsed GAT layers: [256 x 256] x3 ----
    {
        float2 v = dot2<256, 256>(g_packed + OFF_G0, t, A0, A1, gat_b[t]);
        B0[t] = fmaxf(v.x, 0.f); B1[t] = fmaxf(v.y, 0.f);
    }
    __syncthreads();
    {
        float2 v = dot2<256, 256>(g_packed + OFF_G1, t, B0, B1, gat_b[256 + t]);
        A0[t] = fmaxf(v.x, 0.f); A1[t] = fmaxf(v.y, 0.f);
    }
    __syncthreads();
    {
        float2 v = dot2<256, 256>(g_packed + OFF_G2, t, A0, A1, gat_b[512 + t]);
        B0[t] = fmaxf(v.x, 0.f); B1[t] = fmaxf(v.y, 0.f);
        // append company embeddings -> B[256..319]
        if (t < 64) {
            int ci = cidx[r0];
            B0[256 + t] = emb[ci * 64 + t];
        } else if (t < 128) {
            int j = t - 64;
            int ci = cidx[r1];
            B1[256 + j] = emb[ci * 64 + j];
        }
    }
    __syncthreads();

    // ---- fuse: [256 x 320] ----
    {
        float2 v = dot2<256, 320>(g_packed + OFF_F, t, B0, B1, b_fuse[t]);
        A0[t] = fmaxf(v.x, 0.f); A1[t] = fmaxf(v.y, 0.f);
    }
    __syncthreads();

    // ---- stage1 heads: [p1 ; d1] = [256 x 256] ----
    {
        float bias = (t < 128) ? b_p1[t] : b_d1[t - 128];
        float2 v = dot2<256, 256>(g_packed + OFF_S1, t, A0, A1, bias);
        B0[t] = fmaxf(v.x, 0.f); B1[t] = fmaxf(v.y, 0.f);
    }
    __syncthreads();

    // ---- stage2 heads: p2 over B[0..127], d2 over B[128..255], each [64 x 128] ----
    if (t < 128) {
        int tl = t & 63;
        bool is_p = (t < 64);
        const float* P  = is_p ? (g_packed + OFF_P2) : (g_packed + OFF_D2);
        const float* i0 = is_p ? B0 : (B0 + 128);
        const float* i1 = is_p ? B1 : (B1 + 128);
        float bias = is_p ? b_p2[tl] : b_d2[tl];
        float2 v = dot2<64, 128>(P, tl, i0, i1, bias);
        A0[t] = fmaxf(v.x, 0.f); A1[t] = fmaxf(v.y, 0.f);
    }
    __syncthreads();

    // ---- final 64-dots via warp shuffles ----
    const int w = t >> 5, l = t & 31;
    if (w == 0) {
        // price = W_p3 . p2 + b_p3   (p2 in A*[0..63])
        float p0 = W_p3[l] * A0[l] + W_p3[l + 32] * A0[l + 32];
        float p1 = W_p3[l] * A1[l] + W_p3[l + 32] * A1[l + 32];
        #pragma unroll
        for (int m = 16; m >= 1; m >>= 1) {
            p0 += __shfl_xor_sync(0xffffffffu, p0, m);
            p1 += __shfl_xor_sync(0xffffffffu, p1, m);
        }
        if (l == 0) {
            out[r0] = p0 + b_p3[0];
            out[r1] = p1 + b_p3[0];
        }
    } else if (w == 1) {
        // direction = sigmoid(W_d3 . d2 + b_d3)   (d2 in A*[64..127])
        float d0 = W_d3[l] * A0[64 + l] + W_d3[l + 32] * A0[96 + l];
        float d1 = W_d3[l] * A1[64 + l] + W_d3[l + 32] * A1[96 + l];
        #pragma unroll
        for (int m = 16; m >= 1; m >>= 1) {
            d0 += __shfl_xor_sync(0xffffffffu, d0, m);
            d1 += __shfl_xor_sync(0xffffffffu, d1, m);
        }
        if (l == 0) {
            out[64 + r0] = 1.f / (1.f + expf(-(d0 + b_d3[0])));
            out[64 + r1] = 1.f / (1.f + expf(-(d1 + b_d3[0])));
        }
    }
}

extern "C" void kernel_launch(void* const* d_in, const int* in_sizes, int n_in,
                              void* d_out, int out_size) {
    const float* x      = (const float*)d_in[0];
    const int*   cidx   = (const int*)  d_in[1];
    // d_in[2] edge_index, d_in[3] edge_attr: provably unused (softmax collapse)
    const float* W_in   = (const float*)d_in[4];
    const float* b_in   = (const float*)d_in[5];
    const float* gat_W  = (const float*)d_in[6];
    // d_in[7..10]: attention params — unused (collapse)
    const float* gat_b  = (const float*)d_in[11];
    const float* emb    = (const float*)d_in[12];
    const float* W_fuse = (const float*)d_in[13];
    const float* b_fuse = (const float*)d_in[14];
    const float* W_p1   = (const float*)d_in[15];
    const float* b_p1   = (const float*)d_in[16];
    const float* W_p2   = (const float*)d_in[17];
    const float* b_p2   = (const float*)d_in[18];
    const float* W_p3   = (const float*)d_in[19];
    const float* b_p3   = (const float*)d_in[20];
    const float* W_d1   = (const float*)d_in[21];
    const float* b_d1   = (const float*)d_in[22];
    const float* W_d2   = (const float*)d_in[23];
    const float* b_d2   = (const float*)d_in[24];
    const float* W_d3   = (const float*)d_in[25];
    const float* b_d3   = (const float*)d_in[26];

    pack_kernel<<<128, 256>>>(W_in, gat_W, W_fuse, W_p1, W_d1, W_p2, W_d2);
    gat_collapse_kernel<<<32, 256>>>(x, cidx, b_in, gat_b, emb, b_fuse,
                                     b_p1, b_d1, b_p2, b_d2,
                                     W_p3, b_p3, W_d3, b_d3, (float*)d_out);
}

// round 2
// speedup vs baseline: 2.1633x; 2.1633x over previous
#include <cuda_runtime.h>

// ---------------------------------------------------------------------------
// GAT collapses (uniform node features + softmax weights summing to 1 via
// self-loops) => whole model is a 7-layer MLP on 64 rows.
// This version: ONE persistent kernel, 128 blocks co-resident, outputs
// partitioned across blocks, grid barriers between layers.
// Activation layout: k-major float4 [k4][64 rows] -> coalesced act loads,
// warp-broadcast weight loads (native row-major weights, no repacking).
// ---------------------------------------------------------------------------

typedef unsigned long long ULL;

__device__ __forceinline__ void ffma2(ULL& d, ULL a, ULL b) {
    asm("fma.rn.f32x2 %0, %1, %2, %0;" : "+l"(d) : "l"(a), "l"(b));
}
__device__ __forceinline__ float2 unpack2f(ULL v) {
    float2 f; asm("mov.b64 {%0, %1}, %2;" : "=f"(f.x), "=f"(f.y) : "l"(v)); return f;
}

// Ping-pong activation buffers: [80 k-quads][64 rows] of float4 (80 KB each).
__device__ __align__(16) float4 gA[80 * 64];
__device__ __align__(16) float4 gB[80 * 64];
// Monotonic barrier counters (never reset; target = old - old%128 + 128).
__device__ int g_bar[16];

#define NBLK 128

__device__ __forceinline__ void gbar(int idx) {
    __syncthreads();
    if (threadIdx.x == 0) {
        __threadfence();
        int old = atomicAdd(&g_bar[idx], 1);
        int target = old - (old & (NBLK - 1)) + NBLK;
        int cur;
        do {
            asm volatile("ld.acquire.gpu.global.s32 %0, [%1];"
                         : "=r"(cur) : "l"(g_bar + idx) : "memory");
        } while (cur < target);
    }
    __syncthreads();
}

// One layer slice: this thread contributes half the K-dim dot for output `o`,
// row `rg`. actin is [k4][64] float4. Result written by lanes 0..15.
template<int KQ>
__device__ __forceinline__ void layer(const float* __restrict__ Wrow, float bias,
                                      const float4* __restrict__ actin,
                                      float* __restrict__ actout,
                                      int o, int rg, int kh, int lane,
                                      bool do_relu) {
    constexpr int HALF = KQ / 2;
    const longlong2* w4 = (const longlong2*)Wrow + kh * HALF;
    const longlong2* a4 = (const longlong2*)(actin + kh * HALF * 64 + rg);
    ULL acc0 = 0ull, acc1 = 0ull;
    #pragma unroll 16
    for (int i = 0; i < HALF; i++) {
        longlong2 w = w4[i];          // broadcast across warp (same o)
        longlong2 a = a4[(ULL)i * 64];// coalesced across lanes (rows)
        ffma2(acc0, (ULL)w.x, (ULL)a.x);
        ffma2(acc1, (ULL)w.y, (ULL)a.y);
    }
    float2 f0 = unpack2f(acc0), f1 = unpack2f(acc1);
    float s = (f0.x + f0.y) + (f1.x + f1.y);
    s += __shfl_xor_sync(0xffffffffu, s, 16);
    if (lane < 16) {
        float v = s + bias;
        if (do_relu) v = fmaxf(v, 0.f);
        actout[((o >> 2) * 64 + rg) * 4 + (o & 3)] = v;
    }
}

__global__ __launch_bounds__(256, 1) void net_kernel(
    const float* __restrict__ x, const int* __restrict__ cidx,
    const float* __restrict__ W_in, const float* __restrict__ b_in,
    const float* __restrict__ gat_W, const float* __restrict__ gat_b,
    const float* __restrict__ emb,
    const float* __restrict__ W_fuse, const float* __restrict__ b_fuse,
    const float* __restrict__ W_p1, const float* __restrict__ b_p1,
    const float* __restrict__ W_p2, const float* __restrict__ b_p2,
    const float* __restrict__ W_p3, const float* __restrict__ b_p3,
    const float* __restrict__ W_d1, const float* __restrict__ b_d1,
    const float* __restrict__ W_d2, const float* __restrict__ b_d2,
    const float* __restrict__ W_d3, const float* __restrict__ b_d3,
    float* __restrict__ out) {

    const int t    = threadIdx.x;
    const int bx   = blockIdx.x;
    const int g    = bx >> 5;        // row group 0..3 (16 rows each)
    const int gblk = bx & 31;        // out-slice within group
    const int w    = t >> 5;         // warp 0..7
    const int lane = t & 31;
    const int rloc = lane & 15;
    const int kh   = lane >> 4;      // K-half
    const int rg   = g * 16 + rloc;  // global row
    const int o    = gblk * 8 + w;   // global output feature 0..255

    float* A = (float*)gA;
    float* B = (float*)gB;

    // ---- stage: x -> B quads [0..15], emb[cidx] -> B quads [64..79] ----
    if (bx < 4) {
        int q = bx * 256 + t;              // 1024 quads of x
        int r = q >> 4, k4 = q & 15;
        gB[k4 * 64 + r] = ((const float4*)x)[r * 16 + k4];
    } else if (bx < 8) {
        int q = (bx - 4) * 256 + t;        // 1024 quads of emb gather
        int r = q >> 4, k4 = q & 15;
        int ci = cidx[r];
        gB[(64 + k4) * 64 + r] = ((const float4*)emb)[ci * 16 + k4];
    }
    gbar(0);

    // ---- L0: in-layer [256 x 64], B->A ----
    layer<16>(W_in + o * 64, b_in[o], gB, A, o, rg, kh, lane, true);
    gbar(1);
    // ---- L1..L3: collapsed GAT [256 x 256] ----
    layer<64>(gat_W + 0 * 65536 + o * 256, gat_b[0 * 256 + o], gA, B, o, rg, kh, lane, true);
    gbar(2);
    layer<64>(gat_W + 1 * 65536 + o * 256, gat_b[1 * 256 + o], gB, A, o, rg, kh, lane, true);
    gbar(3);
    layer<64>(gat_W + 2 * 65536 + o * 256, gat_b[2 * 256 + o], gA, B, o, rg, kh, lane, true);
    gbar(4);
    // ---- L4: fuse [256 x 320] over [g ; emb], B->A ----
    layer<80>(W_fuse + o * 320, b_fuse[o], gB, A, o, rg, kh, lane, true);
    gbar(5);
    // ---- L5: heads stage1, [p1 ; d1] = [256 x 256], A->B ----
    {
        const float* Wp = (o < 128) ? (W_p1 + o * 256) : (W_d1 + (o - 128) * 256);
        float bb        = (o < 128) ? b_p1[o] : b_d1[o - 128];
        layer<64>(Wp, bb, gA, B, o, rg, kh, lane, true);
    }
    gbar(6);
    // ---- L6: heads stage2, p2/d2 each [64 x 128], B->A (outs 0..127) ----
    if (gblk < 16) {
        int o6 = gblk * 8 + w;  // 0..127
        const float* Wp; float bb; const float4* in;
        if (o6 < 64) { Wp = W_p2 + o6 * 128;        bb = b_p2[o6];      in = gB; }
        else         { Wp = W_d2 + (o6 - 64) * 128; bb = b_d2[o6 - 64]; in = gB + 32 * 64; }
        layer<32>(Wp, bb, in, A, o6, rg, kh, lane, true);
    }
    gbar(7);
    // ---- L7: final dots (K=64 each), one block per group ----
    if (gblk == 0) {
        int item = t >> 3, sl = t & 7;   // 32 items (16 rows x {price,dir}) x 8-way K split
        int r = item >> 1, isdir = item & 1;
        int rgl = g * 16 + r;
        const float* W3 = isdir ? W_d3 : W_p3;
        float s = 0.f;
        #pragma unroll
        for (int j = 0; j < 2; j++) {
            int k4 = sl * 2 + j;
            float4 wv = ((const float4*)W3)[k4];
            float4 av = gA[(isdir * 16 + k4) * 64 + rgl];
            s += wv.x * av.x + wv.y * av.y + wv.z * av.z + wv.w * av.w;
        }
        #pragma unroll
        for (int off = 4; off; off >>= 1)
            s += __shfl_down_sync(0xffffffffu, s, off, 8);
        if (sl == 0) {
            if (!isdir) out[rgl] = s + b_p3[0];
            else        out[64 + rgl] = 1.f / (1.f + expf(-(s + b_d3[0])));
        }
    }
}

extern "C" void kernel_launch(void* const* d_in, const int* in_sizes, int n_in,
                              void* d_out, int out_size) {
    const float* x      = (const float*)d_in[0];
    const int*   cidx   = (const int*)  d_in[1];
    // d_in[2] edge_index, d_in[3] edge_attr: unused (softmax collapse)
    const float* W_in   = (const float*)d_in[4];
    const float* b_in   = (const float*)d_in[5];
    const float* gat_W  = (const float*)d_in[6];
    // d_in[7..10]: attention params — unused (collapse)
    const float* gat_b  = (const float*)d_in[11];
    const float* emb    = (const float*)d_in[12];
    const float* W_fuse = (const float*)d_in[13];
    const float* b_fuse = (const float*)d_in[14];
    const float* W_p1   = (const float*)d_in[15];
    const float* b_p1   = (const float*)d_in[16];
    const float* W_p2   = (const float*)d_in[17];
    const float* b_p2   = (const float*)d_in[18];
    const float* W_p3   = (const float*)d_in[19];
    const float* b_p3   = (const float*)d_in[20];
    const float* W_d1   = (const float*)d_in[21];
    const float* b_d1   = (const float*)d_in[22];
    const float* W_d2   = (const float*)d_in[23];
    const float* b_d2   = (const float*)d_in[24];
    const float* W_d3   = (const float*)d_in[25];
    const float* b_d3   = (const float*)d_in[26];

    net_kernel<<<NBLK, 256>>>(x, cidx, W_in, b_in, gat_W, gat_b, emb,
                              W_fuse, b_fuse, W_p1, b_p1, W_p2, b_p2,
                              W_p3, b_p3, W_d1, b_d1, W_d2, b_d2,
                              W_d3, b_d3, (float*)d_out);
}